// round 11
// baseline (speedup 1.0000x reference)
#include <cuda_runtime.h>

// Problem dims
#define IN_   26
#define INP_  28             // padded to even pairs (pad weights = 0)
#define H1_   64
#define H2_   32
#define F1_   16
#define OUT_  10
#define T_    1000
#define B_    512
#define NB    4              // batch elements per block
#define NTHREADS 256
#define NBLOCKS (B_ / NB)    // 128
#define XQ    7              // 28/4 input quads
#define H1Q   16             // 64/4
#define H2Q   8              // 32/4

typedef unsigned long long u64;

// Shared memory (~55 KB). All sub-arrays 16B-aligned by construction.
struct Smem {
    float xsT[2][NB][32];      // transposed x: [buf][lane][i], i 26..31 zero
    float h1T[2][NB][H1_];     // double-buffered transposed h1: [buf][lane][j]
    float h2T[2][NB][H2_];     // double-buffered transposed h2
    float wih2q[H1Q][128][4];  // LSTM2 weight quads, permuted per-thread (32 KB)
    float whh2q[H2Q][128][4];  // (16 KB)
    float wfc1[F1_ * H2_];
    float bfc1[F1_];
    float wfc2[OUT_ * F1_];
    float bfc2[OUT_];
    float fc1s[NB][F1_];
};

// ---- packed f32x2 helpers ----
__device__ __forceinline__ void ffma2(u64& acc, u64 a, u64 b) {
    asm("fma.rn.f32x2 %0, %1, %2, %0;" : "+l"(acc) : "l"(a), "l"(b));
}
__device__ __forceinline__ u64 pack2(float lo, float hi) {
    u64 r;
    asm("mov.b64 %0, {%1, %2};" : "=l"(r) : "f"(lo), "f"(hi));
    return r;
}
__device__ __forceinline__ float hadd2(u64 v) {
    float2 r;
    asm("mov.b64 {%0, %1}, %2;" : "=f"(r.x), "=f"(r.y) : "l"(v));
    return r.x + r.y;
}
__device__ __forceinline__ float tanh_fast(float x) {
    float y;
    asm("tanh.approx.f32 %0, %1;" : "=f"(y) : "f"(x));
    return y;
}

// Warp-local LSTM cell update. Lane layout: type = lane>>3, off = lane&7.
// Collects f,g,o from lanes type1/2/3 via shfl; type0 lanes (holding i) own
// the register-resident c and write h to smem. All 32 lanes must be converged.
__device__ __forceinline__ void cell_update(float4 a, float4& c, int type,
                                            float* hdst, int stride, int u) {
    float4 fv, gv, ov;
    fv.x = __shfl_down_sync(0xffffffffu, a.x, 8);
    fv.y = __shfl_down_sync(0xffffffffu, a.y, 8);
    fv.z = __shfl_down_sync(0xffffffffu, a.z, 8);
    fv.w = __shfl_down_sync(0xffffffffu, a.w, 8);
    gv.x = __shfl_down_sync(0xffffffffu, a.x, 16);
    gv.y = __shfl_down_sync(0xffffffffu, a.y, 16);
    gv.z = __shfl_down_sync(0xffffffffu, a.z, 16);
    gv.w = __shfl_down_sync(0xffffffffu, a.w, 16);
    ov.x = __shfl_down_sync(0xffffffffu, a.x, 24);
    ov.y = __shfl_down_sync(0xffffffffu, a.y, 24);
    ov.z = __shfl_down_sync(0xffffffffu, a.z, 24);
    ov.w = __shfl_down_sync(0xffffffffu, a.w, 24);
    if (type == 0) {
        c.x = fmaf(fv.x, c.x, a.x * gv.x);
        c.y = fmaf(fv.y, c.y, a.y * gv.y);
        c.z = fmaf(fv.z, c.z, a.z * gv.z);
        c.w = fmaf(fv.w, c.w, a.w * gv.w);
        hdst[0 * stride + u] = ov.x * tanh_fast(c.x);
        hdst[1 * stride + u] = ov.y * tanh_fast(c.y);
        hdst[2 * stride + u] = ov.z * tanh_fast(c.z);
        hdst[3 * stride + u] = ov.w * tanh_fast(c.w);
    }
}

__global__ __launch_bounds__(NTHREADS, 1)
void audio_lstm_kernel(const float* __restrict__ x,
                       const float* __restrict__ w_ih1, const float* __restrict__ w_hh1,
                       const float* __restrict__ b_ih1, const float* __restrict__ b_hh1,
                       const float* __restrict__ w_ih2, const float* __restrict__ w_hh2,
                       const float* __restrict__ b_ih2, const float* __restrict__ b_hh2,
                       const float* __restrict__ w_fc1, const float* __restrict__ b_fc1,
                       const float* __restrict__ w_fc2, const float* __restrict__ b_fc2,
                       float* __restrict__ out)
{
    extern __shared__ unsigned char smem_raw[];
    Smem& s = *reinterpret_cast<Smem*>(smem_raw);

    const int tid  = threadIdx.x;
    const int blk  = blockIdx.x;
    const int lane = tid & 31;
    const int wrp  = tid >> 5;
    const int type = lane >> 3;       // 0:i 1:f 2:g 3:o
    const int off  = lane & 7;
    const int u1   = 8 * wrp + off;   // my LSTM1 unit (0..63)
    const int g1   = type * H1_ + u1; // my LSTM1 gate row
    const bool has2 = (wrp < 4);
    const int u2   = 8 * wrp + off;   // my LSTM2 unit (warps 0-3: 0..31)
    const int g2   = has2 ? (type * H2_ + u2) : 0;

    // ---- Preamble: stage LSTM2 weights permuted so thread p reads slot p ----
    // Thread p (0..127) needs gate row G(p) = ((p>>3)&3)*32 + (p>>5)*8 + (p&7).
    for (int e = tid; e < H1Q * 128 * 4; e += NTHREADS) {
        int m = e >> 9, p = (e >> 2) & 127, q = e & 3;
        int gp = ((p >> 3) & 3) * H2_ + (p >> 5) * 8 + (p & 7);
        s.wih2q[m][p][q] = w_ih2[gp * H1_ + 4 * m + q];
    }
    for (int e = tid; e < H2Q * 128 * 4; e += NTHREADS) {
        int m = e >> 9, p = (e >> 2) & 127, q = e & 3;
        int gp = ((p >> 3) & 3) * H2_ + (p >> 5) * 8 + (p & 7);
        s.whh2q[m][p][q] = w_hh2[gp * H2_ + 4 * m + q];
    }
    for (int e = tid; e < F1_ * H2_; e += NTHREADS) s.wfc1[e] = w_fc1[e];
    if (tid < F1_)  s.bfc1[tid] = b_fc1[tid];
    for (int e = tid; e < OUT_ * F1_; e += NTHREADS) s.wfc2[e] = w_fc2[e];
    if (tid < OUT_) s.bfc2[tid] = b_fc2[tid];

    // Zero states and x buffers (pads must stay finite).
    for (int e = tid; e < 2 * NB * 32; e += NTHREADS) (&s.xsT[0][0][0])[e] = 0.f;
    for (int e = tid; e < 2 * NB * H1_; e += NTHREADS) (&s.h1T[0][0][0])[e] = 0.f;
    for (int e = tid; e < 2 * NB * H2_; e += NTHREADS) (&s.h2T[0][0][0])[e] = 0.f;

    // LSTM1 weights register-resident as j-pairs {w[2m],w[2m+1]}: 46 u64.
    u64 wxp[INP_ / 2], whp[H1_ / 2];
    #pragma unroll
    for (int m = 0; m < INP_ / 2; m++) {
        float lo = (2 * m     < IN_) ? w_ih1[g1 * IN_ + 2 * m]     : 0.f;
        float hi = (2 * m + 1 < IN_) ? w_ih1[g1 * IN_ + 2 * m + 1] : 0.f;
        wxp[m] = pack2(lo, hi);
    }
    #pragma unroll
    for (int m = 0; m < H1_ / 2; m++)
        whp[m] = pack2(w_hh1[g1 * H1_ + 2 * m], w_hh1[g1 * H1_ + 2 * m + 1]);
    const float b1s = b_ih1[g1] + b_hh1[g1];
    const float b2s = has2 ? (b_ih2[g2] + b_hh2[g2]) : 0.f;

    // Uniform activation constants: gate = fma(tanh(As*v + Ab), Am, Ac)
    // sigmoid: 0.5*tanh(0.5v + 0.5b)+0.5 ; tanh: tanh(v + b).
    const float As = (type == 2) ? 1.f : 0.5f;
    const float Am = As;
    const float Ac = (type == 2) ? 0.f : 0.5f;
    const float Ab1 = As * b1s;
    const float Ab2 = As * b2s;

    // Register-resident cell states (live in type-0 lanes).
    float4 c1r = make_float4(0.f, 0.f, 0.f, 0.f);
    float4 c2r = make_float4(0.f, 0.f, 0.f, 0.f);

    // x loaders in warps 4-7. x[b,0,i,t] at b*IN*T + i*T + t.
    const int lidx = tid - 128;
    const bool is_loader = (lidx >= 0) && (lidx < NB * IN_);
    const int xi = is_loader ? (lidx % IN_) : 0;
    const int xb = is_loader ? (lidx / IN_) : 0;
    const float* xptr = x + (size_t)(blk * NB + xb) * IN_ * T_ + (size_t)xi * T_;
    __syncthreads();
    if (is_loader) s.xsT[0][xb][xi] = xptr[0];
    __syncthreads();

    // ---- Main loop: ONE barrier per step ----
    // Iter k: LSTM1 gates+update (k) on all warps; LSTM2 gates+update (k-1)
    // fused on warps 0-3 (sharing h1 reads). All state double-buffered:
    // read [buf], write [buf^1]; end-of-step barrier covers WAR + STS drain.
    int buf = 0;
    #pragma unroll 1
    for (int k = 0; k <= T_; k++) {
        const bool do1 = (k < T_);
        const bool do2 = (k > 0);

        const bool pre = do1 && is_loader && (k + 1 < T_);
        if (pre) s.xsT[buf ^ 1][xb][xi] = xptr[k + 1];

        if (do1 && has2 && do2) {
            // ---- Fused: LSTM1 gate (k) + LSTM2 gate (k-1), shared h1 reads ----
            u64 aL[NB] = {0, 0, 0, 0};
            u64 dL[NB] = {0, 0, 0, 0};
            const float* xsb = &s.xsT[buf][0][0];
            const float* h1b = &s.h1T[buf][0][0];
            const float* h2b = &s.h2T[buf][0][0];
            #pragma unroll
            for (int m = 0; m < XQ; m++) {
                #pragma unroll
                for (int l = 0; l < NB; l++) {
                    ulonglong2 xq = *reinterpret_cast<const ulonglong2*>(xsb + 32 * l + 4 * m);
                    ffma2(aL[l], wxp[2 * m], xq.x);
                    ffma2(aL[l], wxp[2 * m + 1], xq.y);
                }
            }
            #pragma unroll
            for (int m = 0; m < H1Q; m++) {
                ulonglong2 wv = *reinterpret_cast<const ulonglong2*>(&s.wih2q[m][tid][0]);
                #pragma unroll
                for (int l = 0; l < NB; l++) {
                    ulonglong2 hq = *reinterpret_cast<const ulonglong2*>(h1b + H1_ * l + 4 * m);
                    ffma2(aL[l], whp[2 * m], hq.x);
                    ffma2(aL[l], whp[2 * m + 1], hq.y);
                    ffma2(dL[l], wv.x, hq.x);
                    ffma2(dL[l], wv.y, hq.y);
                }
            }
            #pragma unroll
            for (int m = 0; m < H2Q; m++) {
                ulonglong2 wv = *reinterpret_cast<const ulonglong2*>(&s.whh2q[m][tid][0]);
                #pragma unroll
                for (int l = 0; l < NB; l++) {
                    ulonglong2 hq = *reinterpret_cast<const ulonglong2*>(h2b + H2_ * l + 4 * m);
                    ffma2(dL[l], wv.x, hq.x);
                    ffma2(dL[l], wv.y, hq.y);
                }
            }
            float4 a, d;
            float* ap = &a.x; float* dp = &d.x;
            #pragma unroll
            for (int l = 0; l < NB; l++) {
                ap[l] = fmaf(tanh_fast(fmaf(As, hadd2(aL[l]), Ab1)), Am, Ac);
                dp[l] = fmaf(tanh_fast(fmaf(As, hadd2(dL[l]), Ab2)), Am, Ac);
            }
            cell_update(a, c1r, type, &s.h1T[buf ^ 1][0][0], H1_, u1);
            cell_update(d, c2r, type, &s.h2T[buf ^ 1][0][0], H2_, u2);
        } else if (do1) {
            // ---- LSTM1 only (warps 4-7 always; warps 0-3 at k==0) ----
            u64 aL[NB] = {0, 0, 0, 0};
            const float* xsb = &s.xsT[buf][0][0];
            const float* h1b = &s.h1T[buf][0][0];
            #pragma unroll
            for (int m = 0; m < XQ; m++) {
                #pragma unroll
                for (int l = 0; l < NB; l++) {
                    ulonglong2 xq = *reinterpret_cast<const ulonglong2*>(xsb + 32 * l + 4 * m);
                    ffma2(aL[l], wxp[2 * m], xq.x);
                    ffma2(aL[l], wxp[2 * m + 1], xq.y);
                }
            }
            #pragma unroll
            for (int m = 0; m < H1Q; m++) {
                #pragma unroll
                for (int l = 0; l < NB; l++) {
                    ulonglong2 hq = *reinterpret_cast<const ulonglong2*>(h1b + H1_ * l + 4 * m);
                    ffma2(aL[l], whp[2 * m], hq.x);
                    ffma2(aL[l], whp[2 * m + 1], hq.y);
                }
            }
            float4 a; float* ap = &a.x;
            #pragma unroll
            for (int l = 0; l < NB; l++)
                ap[l] = fmaf(tanh_fast(fmaf(As, hadd2(aL[l]), Ab1)), Am, Ac);
            cell_update(a, c1r, type, &s.h1T[buf ^ 1][0][0], H1_, u1);
        } else if (has2) {
            // ---- k == T_: final LSTM2 gates (step T-1) + update ----
            u64 dL[NB] = {0, 0, 0, 0};
            const float* h1b = &s.h1T[buf][0][0];
            const float* h2b = &s.h2T[buf][0][0];
            #pragma unroll
            for (int m = 0; m < H1Q; m++) {
                ulonglong2 wv = *reinterpret_cast<const ulonglong2*>(&s.wih2q[m][tid][0]);
                #pragma unroll
                for (int l = 0; l < NB; l++) {
                    ulonglong2 hq = *reinterpret_cast<const ulonglong2*>(h1b + H1_ * l + 4 * m);
                    ffma2(dL[l], wv.x, hq.x);
                    ffma2(dL[l], wv.y, hq.y);
                }
            }
            #pragma unroll
            for (int m = 0; m < H2Q; m++) {
                ulonglong2 wv = *reinterpret_cast<const ulonglong2*>(&s.whh2q[m][tid][0]);
                #pragma unroll
                for (int l = 0; l < NB; l++) {
                    ulonglong2 hq = *reinterpret_cast<const ulonglong2*>(h2b + H2_ * l + 4 * m);
                    ffma2(dL[l], wv.x, hq.x);
                    ffma2(dL[l], wv.y, hq.y);
                }
            }
            float4 d; float* dp = &d.x;
            #pragma unroll
            for (int l = 0; l < NB; l++)
                dp[l] = fmaf(tanh_fast(fmaf(As, hadd2(dL[l]), Ab2)), Am, Ac);
            cell_update(d, c2r, type, &s.h2T[buf ^ 1][0][0], H2_, u2);
        }

        __syncthreads();
        buf ^= 1;
    }

    // ---- FC head on final h2 = h2(T-1), now in h2T[buf] ----
    if (tid < NB * F1_) {
        int b = tid >> 4, f = tid & 15;
        float acc = s.bfc1[f];
        #pragma unroll
        for (int k = 0; k < H2_; k++)
            acc = fmaf(s.h2T[buf][b][k], s.wfc1[f * H2_ + k], acc);
        s.fc1s[b][f] = fmaxf(acc, 0.f);
    }
    __syncthreads();
    if (tid < NB * OUT_) {
        int b = tid / OUT_, o = tid % OUT_;
        float acc = s.bfc2[o];
        #pragma unroll
        for (int f = 0; f < F1_; f++)
            acc = fmaf(s.fc1s[b][f], s.wfc2[o * F1_ + f], acc);
        out[(blk * NB + b) * OUT_ + o] = acc;
    }
}

extern "C" void kernel_launch(void* const* d_in, const int* in_sizes, int n_in,
                              void* d_out, int out_size)
{
    const float* x     = (const float*)d_in[0];
    const float* w_ih1 = (const float*)d_in[1];
    const float* w_hh1 = (const float*)d_in[2];
    const float* b_ih1 = (const float*)d_in[3];
    const float* b_hh1 = (const float*)d_in[4];
    const float* w_ih2 = (const float*)d_in[5];
    const float* w_hh2 = (const float*)d_in[6];
    const float* b_ih2 = (const float*)d_in[7];
    const float* b_hh2 = (const float*)d_in[8];
    const float* w_fc1 = (const float*)d_in[9];
    const float* b_fc1 = (const float*)d_in[10];
    const float* w_fc2 = (const float*)d_in[11];
    const float* b_fc2 = (const float*)d_in[12];
    float* out = (float*)d_out;

    static_assert(sizeof(Smem) < 220 * 1024, "smem too big");
    cudaFuncSetAttribute(audio_lstm_kernel,
                         cudaFuncAttributeMaxDynamicSharedMemorySize,
                         (int)sizeof(Smem));

    audio_lstm_kernel<<<NBLOCKS, NTHREADS, sizeof(Smem)>>>(
        x, w_ih1, w_hh1, b_ih1, b_hh1,
        w_ih2, w_hh2, b_ih2, b_hh2,
        w_fc1, b_fc1, w_fc2, b_fc2, out);
}